// round 12
// baseline (speedup 1.0000x reference)
#include <cuda_runtime.h>
#include <cstdint>

// CenterLoss: mean_i ||x[i] - centers[labels[i]]||^2
// B=16384, C=4000, D=512
// Inputs: x [B*D] f32, labels [B] int32, centers [C*D] f32. Output: scalar f32.
//
// Body = proven-fastest R2 shape (warp per row, 8 front-batched LDG.128).
// New: single-graph-node reduction — no memsetAsync. Blocks write partials to
// a __device__ scratch array; a self-resetting arrival counter elects the last
// block, which sums partials and plain-stores the output.

#define B_ROWS 16384
#define C_ROWS 4000
#define D_VEC  128               // 512 floats = 128 float4 per row
#define WARPS_PER_BLOCK 8
#define THREADS (WARPS_PER_BLOCK * 32)
#define BLOCKS  (B_ROWS / WARPS_PER_BLOCK)   // 2048

__device__ float    g_partials[BLOCKS];
__device__ unsigned g_arrive;                 // zero-init at load; self-resets

__global__ __launch_bounds__(THREADS)
void center_loss_kernel(const float4* __restrict__ x,
                        const int* __restrict__ labels,
                        const float4* __restrict__ centers,
                        float* __restrict__ out)
{
    const int warp = threadIdx.x >> 5;
    const int lane = threadIdx.x & 31;
    const int row  = blockIdx.x * WARPS_PER_BLOCK + warp;

    int lab = labels[row];
    lab = min(max(lab, 0), C_ROWS - 1);

    const float4* xr = x       + (size_t)row * D_VEC + lane;
    const float4* cr = centers + (size_t)lab * D_VEC + lane;

    // Front-batched 8 LDG.128 per lane (proven-best body).
    float4 a0 = xr[0],  a1 = xr[32], a2 = xr[64], a3 = xr[96];
    float4 b0 = cr[0],  b1 = cr[32], b2 = cr[64], b3 = cr[96];

    float s = 0.0f;
    float dx, dy, dz, dw;
    dx = a0.x - b0.x; dy = a0.y - b0.y; dz = a0.z - b0.z; dw = a0.w - b0.w;
    s += dx*dx + dy*dy + dz*dz + dw*dw;
    dx = a1.x - b1.x; dy = a1.y - b1.y; dz = a1.z - b1.z; dw = a1.w - b1.w;
    s += dx*dx + dy*dy + dz*dz + dw*dw;
    dx = a2.x - b2.x; dy = a2.y - b2.y; dz = a2.z - b2.z; dw = a2.w - b2.w;
    s += dx*dx + dy*dy + dz*dz + dw*dw;
    dx = a3.x - b3.x; dy = a3.y - b3.y; dz = a3.z - b3.z; dw = a3.w - b3.w;
    s += dx*dx + dy*dy + dz*dz + dw*dw;

    // warp reduce
    #pragma unroll
    for (int o = 16; o > 0; o >>= 1)
        s += __shfl_xor_sync(0xFFFFFFFFu, s, o);

    __shared__ float warp_sums[WARPS_PER_BLOCK];
    __shared__ int   is_last;
    if (lane == 0) warp_sums[warp] = s;
    __syncthreads();

    if (threadIdx.x == 0) {
        float v = 0.0f;
        #pragma unroll
        for (int w = 0; w < WARPS_PER_BLOCK; w++) v += warp_sums[w];
        g_partials[blockIdx.x] = v;
        __threadfence();                       // partial visible before arrive
        unsigned old = atomicAdd(&g_arrive, 1u);
        is_last = (old == BLOCKS - 1);
    }
    __syncthreads();

    if (is_last) {
        __threadfence();                       // acquire all partials
        // 2048 partials, 256 threads -> 8 strided loads each.
        float v = 0.0f;
        #pragma unroll
        for (int k = 0; k < BLOCKS / THREADS; k++)
            v += g_partials[threadIdx.x + k * THREADS];

        #pragma unroll
        for (int o = 16; o > 0; o >>= 1)
            v += __shfl_xor_sync(0xFFFFFFFFu, v, o);
        if (lane == 0) warp_sums[warp] = v;
        __syncthreads();

        if (threadIdx.x == 0) {
            float t = 0.0f;
            #pragma unroll
            for (int w = 0; w < WARPS_PER_BLOCK; w++) t += warp_sums[w];
            *out = t * (1.0f / (float)B_ROWS);
            g_arrive = 0;                      // self-reset for next replay
        }
    }
}

extern "C" void kernel_launch(void* const* d_in, const int* in_sizes, int n_in,
                              void* d_out, int out_size)
{
    const float4* x       = (const float4*)d_in[0];
    const int*    labels  = (const int*)d_in[1];
    const float4* centers = (const float4*)d_in[2];
    float*        out     = (float*)d_out;

    // Single graph node: no memset, out written by plain store.
    center_loss_kernel<<<BLOCKS, THREADS>>>(x, labels, centers, out);
}

// round 13
// speedup vs baseline: 1.0997x; 1.0997x over previous
#include <cuda_runtime.h>
#include <cstdint>

// CenterLoss: mean_i ||x[i] - centers[labels[i]]||^2
// B=16384, C=4000, D=512
// Inputs: x [B*D] f32, labels [B] int32, centers [C*D] f32. Output: scalar f32.
//
// R2 body (proven best: warp/row, 8 front-batched LDG.128, memset+atomic)
// + prefetch.global.L2 of the row consumed one residency-period later:
// wave-2/3 LDGs hit L2 (~240cy) instead of DRAM (~600cy).

#define B_ROWS 16384
#define C_ROWS 4000
#define D_VEC  128               // 512 floats = 128 float4 per row
#define WARPS_PER_BLOCK 8
#define THREADS (WARPS_PER_BLOCK * 32)
#define BLOCKS  (B_ROWS / WARPS_PER_BLOCK)   // 2048
#define PF_DIST 7168             // ~ rows processed by one resident set (896 blocks x 8)

__device__ __forceinline__ void prefetch_l2(const void* p) {
    asm volatile("prefetch.global.L2 [%0];" :: "l"(p));
}

__global__ __launch_bounds__(THREADS)
void center_loss_kernel(const float4* __restrict__ x,
                        const int* __restrict__ labels,
                        const float4* __restrict__ centers,
                        float* __restrict__ out)
{
    const int warp = threadIdx.x >> 5;
    const int lane = threadIdx.x & 31;
    const int row  = blockIdx.x * WARPS_PER_BLOCK + warp;

    // ---- Prefetch the row one residency-period ahead into L2. ----
    const int pf_row = row + PF_DIST;
    if (pf_row < B_ROWS) {
        if (lane < 16) {
            // 16 lanes x 128B = full 2KB x row
            prefetch_l2((const char*)(x + (size_t)pf_row * D_VEC) + lane * 128);
        } else {
            int pl = labels[pf_row];
            pl = min(max(pl, 0), C_ROWS - 1);
            prefetch_l2((const char*)(centers + (size_t)pl * D_VEC) + (lane - 16) * 128);
        }
    }

    // ---- Proven-best body. ----
    int lab = labels[row];
    lab = min(max(lab, 0), C_ROWS - 1);

    const float4* xr = x       + (size_t)row * D_VEC + lane;
    const float4* cr = centers + (size_t)lab * D_VEC + lane;

    float4 a0 = xr[0],  a1 = xr[32], a2 = xr[64], a3 = xr[96];
    float4 b0 = cr[0],  b1 = cr[32], b2 = cr[64], b3 = cr[96];

    float s = 0.0f;
    float dx, dy, dz, dw;
    dx = a0.x - b0.x; dy = a0.y - b0.y; dz = a0.z - b0.z; dw = a0.w - b0.w;
    s += dx*dx + dy*dy + dz*dz + dw*dw;
    dx = a1.x - b1.x; dy = a1.y - b1.y; dz = a1.z - b1.z; dw = a1.w - b1.w;
    s += dx*dx + dy*dy + dz*dz + dw*dw;
    dx = a2.x - b2.x; dy = a2.y - b2.y; dz = a2.z - b2.z; dw = a2.w - b2.w;
    s += dx*dx + dy*dy + dz*dz + dw*dw;
    dx = a3.x - b3.x; dy = a3.y - b3.y; dz = a3.z - b3.z; dw = a3.w - b3.w;
    s += dx*dx + dy*dy + dz*dz + dw*dw;

    #pragma unroll
    for (int o = 16; o > 0; o >>= 1)
        s += __shfl_xor_sync(0xFFFFFFFFu, s, o);

    __shared__ float warp_sums[WARPS_PER_BLOCK];
    if (lane == 0) warp_sums[warp] = s;
    __syncthreads();

    if (warp == 0) {
        float v = (lane < WARPS_PER_BLOCK) ? warp_sums[lane] : 0.0f;
        #pragma unroll
        for (int o = 4; o > 0; o >>= 1)
            v += __shfl_xor_sync(0xFFFFFFFFu, v, o);
        if (lane == 0)
            atomicAdd(out, v * (1.0f / (float)B_ROWS));
    }
}

extern "C" void kernel_launch(void* const* d_in, const int* in_sizes, int n_in,
                              void* d_out, int out_size)
{
    const float4* x       = (const float4*)d_in[0];
    const int*    labels  = (const int*)d_in[1];
    const float4* centers = (const float4*)d_in[2];
    float*        out     = (float*)d_out;

    cudaMemsetAsync(out, 0, sizeof(float));
    center_loss_kernel<<<BLOCKS, THREADS>>>(x, labels, centers, out);
}

// round 14
// speedup vs baseline: 1.2671x; 1.1522x over previous
#include <cuda_runtime.h>
#include <cstdint>

// CenterLoss: mean_i ||x[i] - centers[labels[i]]||^2
// B=16384, C=4000, D=512
// Inputs: x [B*D] f32, labels [B] int32, centers [C*D] f32. Output: scalar f32.
//
// The machine serves ~4 TB/s DRAM reads (measured invariant over 12 designs);
// the plain kernel is at that floor with 41MB/replay. This version shrinks
// per-replay DRAM bytes: x marked L2::evict_first (one-shot stream), centers
// L2::evict_last (stays resident across graph replays) -> steady-state DRAM
// traffic ~32MB, centers served from L2 in parallel.

#define B_ROWS 16384
#define C_ROWS 4000
#define WARPS_PER_BLOCK 8
#define THREADS (WARPS_PER_BLOCK * 32)
#define BLOCKS  (B_ROWS / WARPS_PER_BLOCK)   // 2048

// sm_103a: cache policies on ld.global require .v8.b32 (256-bit).
#define LDG256_EF(v, ptr)                                                     \
    asm volatile("ld.global.L2::evict_first.v8.b32 "                          \
                 "{%0,%1,%2,%3,%4,%5,%6,%7}, [%8];"                           \
                 : "=f"(v[0]), "=f"(v[1]), "=f"(v[2]), "=f"(v[3]),            \
                   "=f"(v[4]), "=f"(v[5]), "=f"(v[6]), "=f"(v[7])             \
                 : "l"(ptr))
#define LDG256_EL(v, ptr)                                                     \
    asm volatile("ld.global.L2::evict_last.v8.b32 "                           \
                 "{%0,%1,%2,%3,%4,%5,%6,%7}, [%8];"                           \
                 : "=f"(v[0]), "=f"(v[1]), "=f"(v[2]), "=f"(v[3]),            \
                   "=f"(v[4]), "=f"(v[5]), "=f"(v[6]), "=f"(v[7])             \
                 : "l"(ptr))

__global__ __launch_bounds__(THREADS)
void center_loss_kernel(const float* __restrict__ x,
                        const int* __restrict__ labels,
                        const float* __restrict__ centers,
                        float* __restrict__ out)
{
    const int warp = threadIdx.x >> 5;
    const int lane = threadIdx.x & 31;
    const int row  = blockIdx.x * WARPS_PER_BLOCK + warp;

    int lab = labels[row];
    lab = min(max(lab, 0), C_ROWS - 1);

    // Row = 512 floats. Lane covers 8 floats per pass, 2 passes per side.
    const float* xr = x       + (size_t)row * 512 + lane * 8;
    const float* cr = centers + (size_t)lab * 512 + lane * 8;

    float a0[8], a1[8], b0[8], b1[8];
    LDG256_EF(a0, xr);          // x: stream, evict first
    LDG256_EF(a1, xr + 256);
    LDG256_EL(b0, cr);          // centers: keep resident in L2
    LDG256_EL(b1, cr + 256);

    float s = 0.0f;
    #pragma unroll
    for (int i = 0; i < 8; i++) {
        const float d0 = a0[i] - b0[i];
        const float d1 = a1[i] - b1[i];
        s += d0 * d0 + d1 * d1;
    }

    // warp reduce
    #pragma unroll
    for (int o = 16; o > 0; o >>= 1)
        s += __shfl_xor_sync(0xFFFFFFFFu, s, o);

    __shared__ float warp_sums[WARPS_PER_BLOCK];
    if (lane == 0) warp_sums[warp] = s;
    __syncthreads();

    if (warp == 0) {
        float v = (lane < WARPS_PER_BLOCK) ? warp_sums[lane] : 0.0f;
        #pragma unroll
        for (int o = 4; o > 0; o >>= 1)
            v += __shfl_xor_sync(0xFFFFFFFFu, v, o);
        if (lane == 0)
            atomicAdd(out, v * (1.0f / (float)B_ROWS));
    }
}

extern "C" void kernel_launch(void* const* d_in, const int* in_sizes, int n_in,
                              void* d_out, int out_size)
{
    const float* x       = (const float*)d_in[0];
    const int*   labels  = (const int*)d_in[1];
    const float* centers = (const float*)d_in[2];
    float*       out     = (float*)d_out;

    cudaMemsetAsync(out, 0, sizeof(float));
    center_loss_kernel<<<BLOCKS, THREADS>>>(x, labels, centers, out);
}